// round 1
// baseline (speedup 1.0000x reference)
#include <cuda_runtime.h>
#include <cuda_bf16.h>

// Problem constants (fixed shapes from setup_inputs)
#define N_TOTAL 8192
#define B_HALF  4096
#define D       256
#define TILE    128
#define BK      16
#define NT      256
#define NTILES  (N_TOTAL / TILE)   // 64
#define HTILES  (B_HALF / TILE)    // 32

// Scratch (device globals: no allocations allowed)
__device__ float  g_sq[N_TOTAL];
__device__ float  g_colsum[D];
__device__ double g_sumsq;
__device__ double g_acc;
__device__ float  g_m;   // log2(e) / (16 * bandwidth)

__global__ void init_kernel() {
    int t = threadIdx.x;
    if (t < D) g_colsum[t] = 0.f;
    if (t == 0) { g_sumsq = 0.0; g_acc = 0.0; }
}

// One warp per row: squared L2 norm of each row; block-accumulate sum of norms.
__global__ void rownorm_kernel(const float* __restrict__ xs,
                               const float* __restrict__ xt) {
    int warp = threadIdx.x >> 5, lane = threadIdx.x & 31;
    int row  = blockIdx.x * 8 + warp;
    const float* p = (row < B_HALF) ? xs + (size_t)row * D
                                    : xt + (size_t)(row - B_HALF) * D;
    float s = 0.f;
    #pragma unroll
    for (int c = lane; c < D; c += 32) { float v = p[c]; s = fmaf(v, v, s); }
    #pragma unroll
    for (int off = 16; off; off >>= 1) s += __shfl_xor_sync(0xffffffffu, s, off);

    __shared__ float wsum[8];
    if (lane == 0) { g_sq[row] = s; wsum[warp] = s; }
    __syncthreads();
    if (threadIdx.x == 0) {
        double b = 0.0;
        #pragma unroll
        for (int w = 0; w < 8; w++) b += (double)wsum[w];
        atomicAdd(&g_sumsq, b);
    }
}

// Column sums (for ||sum of rows||^2 term of sum(L2)).
__global__ void colsum_kernel(const float* __restrict__ xs,
                              const float* __restrict__ xt) {
    int c  = threadIdx.x;       // 0..255 -> coalesced across threads
    int r0 = blockIdx.x * 256;
    float s = 0.f;
    for (int r = r0; r < r0 + 256; r++) {
        const float* p = (r < B_HALF) ? xs + (size_t)r * D
                                      : xt + (size_t)(r - B_HALF) * D;
        s += p[c];
    }
    atomicAdd(&g_colsum[c], s);
}

__global__ void bw_kernel() {
    __shared__ float cs[D];
    int t = threadIdx.x;
    float v = g_colsum[t];
    cs[t] = v * v;
    __syncthreads();
    for (int s = 128; s; s >>= 1) {
        if (t < s) cs[t] += cs[t + s];
        __syncthreads();
    }
    if (t == 0) {
        double n     = (double)N_TOTAL;
        double sumL2 = 2.0 * n * g_sumsq - 2.0 * (double)cs[0];
        double bw    = sumL2 / (n * n - n);
        bw /= 4.0;  // KERNEL_MUL^(KERNEL_NUM//2) = 2^2
        g_m = (float)(1.4426950408889634 / (bw * 16.0));
    }
}

// Main fused kernel: G = T T^T tile, then 5-kernel RBF sum with sign weight.
// Only lower-triangular tile pairs computed; off-diagonal tiles weighted 2x.
__global__ void __launch_bounds__(NT) mmd_kernel(const float* __restrict__ xs,
                                                 const float* __restrict__ xt) {
    int ti = blockIdx.y, tj = blockIdx.x;
    if (tj > ti) return;

    __shared__ float As[BK][TILE];
    __shared__ float Bs[BK][TILE];

    const float* Ab = (ti < HTILES) ? xs + (size_t)ti * TILE * D
                                    : xt + (size_t)(ti - HTILES) * TILE * D;
    const float* Bb = (tj < HTILES) ? xs + (size_t)tj * TILE * D
                                    : xt + (size_t)(tj - HTILES) * TILE * D;

    int tid = threadIdx.x;
    int tx  = tid & 15;          // 0..15 -> 8 cols each
    int ty  = tid >> 4;          // 0..15 -> 8 rows each

    // loader mapping: 512 float4 per (128x16) tile, 2 per thread
    int lr = tid >> 2;           // 0..63 (and +64)
    int lc = (tid & 3) * 4;      // 0,4,8,12

    float acc[8][8] = {};

    for (int k0 = 0; k0 < D; k0 += BK) {
        #pragma unroll
        for (int s = 0; s < 2; s++) {
            int r = lr + s * 64;
            float4 va = *(const float4*)(Ab + (size_t)r * D + k0 + lc);
            As[lc + 0][r] = va.x; As[lc + 1][r] = va.y;
            As[lc + 2][r] = va.z; As[lc + 3][r] = va.w;
            float4 vb = *(const float4*)(Bb + (size_t)r * D + k0 + lc);
            Bs[lc + 0][r] = vb.x; Bs[lc + 1][r] = vb.y;
            Bs[lc + 2][r] = vb.z; Bs[lc + 3][r] = vb.w;
        }
        __syncthreads();

        #pragma unroll
        for (int kk = 0; kk < BK; kk++) {
            float4 a0 = *(const float4*)&As[kk][ty * 8];
            float4 a1 = *(const float4*)&As[kk][ty * 8 + 4];
            float4 b0 = *(const float4*)&Bs[kk][tx * 8];
            float4 b1 = *(const float4*)&Bs[kk][tx * 8 + 4];
            float a[8] = {a0.x, a0.y, a0.z, a0.w, a1.x, a1.y, a1.z, a1.w};
            float b[8] = {b0.x, b0.y, b0.z, b0.w, b1.x, b1.y, b1.z, b1.w};
            #pragma unroll
            for (int i = 0; i < 8; i++)
                #pragma unroll
                for (int j = 0; j < 8; j++)
                    acc[i][j] = fmaf(a[i], b[j], acc[i][j]);
        }
        __syncthreads();
    }

    // Epilogue: L2 -> sum of 5 RBF kernels via one EX2 + squarings.
    float m = g_m;
    float sqa[8], sqb[8];
    #pragma unroll
    for (int i = 0; i < 8; i++) sqa[i] = g_sq[ti * TILE + ty * 8 + i];
    #pragma unroll
    for (int j = 0; j < 8; j++) sqb[j] = g_sq[tj * TILE + tx * 8 + j];

    float sum = 0.f;
    #pragma unroll
    for (int i = 0; i < 8; i++) {
        #pragma unroll
        for (int j = 0; j < 8; j++) {
            float L2 = sqa[i] + sqb[j] - 2.f * acc[i][j];
            L2 = fmaxf(L2, 0.f);
            float t = -L2 * m;
            float e0;
            asm("ex2.approx.ftz.f32 %0, %1;" : "=f"(e0) : "f"(t));
            float e1 = e0 * e0;   // i=3
            float e2 = e1 * e1;   // i=2
            float e3 = e2 * e2;   // i=1
            float e4 = e3 * e3;   // i=0
            sum += ((e0 + e1) + (e2 + e3)) + e4;
        }
    }

    float w = (((ti < HTILES) == (tj < HTILES)) ? 1.f : -1.f) *
              ((ti == tj) ? 1.f : 2.f);
    sum *= w;

    // Block reduction -> one double atomic per block
    #pragma unroll
    for (int off = 16; off; off >>= 1) sum += __shfl_xor_sync(0xffffffffu, sum, off);
    __shared__ float red[NT / 32];
    int lane = tid & 31, wrp = tid >> 5;
    if (lane == 0) red[wrp] = sum;
    __syncthreads();
    if (wrp == 0) {
        float v = (lane < NT / 32) ? red[lane] : 0.f;
        #pragma unroll
        for (int off = 4; off; off >>= 1) v += __shfl_xor_sync(0xffffffffu, v, off);
        if (lane == 0) atomicAdd(&g_acc, (double)v);
    }
}

__global__ void finalize_kernel(float* __restrict__ out) {
    out[0] = (float)(g_acc / ((double)B_HALF * (double)B_HALF));
}

extern "C" void kernel_launch(void* const* d_in, const int* in_sizes, int n_in,
                              void* d_out, int out_size) {
    const float* xs = (const float*)d_in[0];
    const float* xt = (const float*)d_in[1];
    float* out = (float*)d_out;

    init_kernel<<<1, 256>>>();
    rownorm_kernel<<<N_TOTAL / 8, 256>>>(xs, xt);
    colsum_kernel<<<N_TOTAL / 256, 256>>>(xs, xt);
    bw_kernel<<<1, 256>>>();
    dim3 grid(NTILES, NTILES);
    mmd_kernel<<<grid, NT>>>(xs, xt);
    finalize_kernel<<<1, 1>>>(out);
}

// round 3
// speedup vs baseline: 3.8301x; 3.8301x over previous
#include <cuda_runtime.h>
#include <cstdint>

// ---------------- problem constants ----------------
#define NTOT   8192
#define BHALF  4096
#define DD     256
#define TILE   128
#define KC     32       // K-chunk floats = 128 B/row (swizzle atom)
#define NCHUNK 8        // 256 / 32
#define NT     256      // threads per CTA (8 warps, 2x4 warp grid)

// smem: [A0 16K][B0 16K][A1 16K][B1 16K] = 64 KB dynamic
#define STAGE_BYTES 32768u
#define B_OFF       16384u
#define SMEM_TOTAL  65536

// ---------------- device scratch (no allocs allowed) ----------------
__device__ float  g_x[NTOT * DD];      // tf32-rounded inputs, concatenated
__device__ float  g_sq[NTOT];          // row squared norms of rounded data
__device__ float  g_sqpart[1024];
__device__ float  g_colpart[32 * DD];
__device__ float  g_m;                 // log2(e) / (16 * bandwidth)
__device__ double g_acc;

// ---------------- helpers ----------------
__device__ __forceinline__ uint32_t smem_u32(const void* p) {
    uint32_t a;
    asm("{ .reg .u64 t; cvta.to.shared.u64 t, %1; cvt.u32.u64 %0, t; }"
        : "=r"(a) : "l"(p));
    return a;
}

__device__ __forceinline__ void ldsm_x4(uint32_t& r0, uint32_t& r1,
                                        uint32_t& r2, uint32_t& r3,
                                        uint32_t addr) {
    asm volatile("ldmatrix.sync.aligned.m8n8.x4.shared.b16 {%0,%1,%2,%3}, [%4];"
                 : "=r"(r0), "=r"(r1), "=r"(r2), "=r"(r3) : "r"(addr));
}

__device__ __forceinline__ void mma_tf32(float* d, const uint32_t* a,
                                         uint32_t b0, uint32_t b1) {
    asm volatile(
        "mma.sync.aligned.m16n8k8.row.col.f32.tf32.tf32.f32 "
        "{%0,%1,%2,%3}, {%4,%5,%6,%7}, {%8,%9}, {%0,%1,%2,%3};"
        : "+f"(d[0]), "+f"(d[1]), "+f"(d[2]), "+f"(d[3])
        : "r"(a[0]), "r"(a[1]), "r"(a[2]), "r"(a[3]), "r"(b0), "r"(b1));
}

// ---------------- prep kernels ----------------
__global__ void convert_kernel(const float* __restrict__ xs,
                               const float* __restrict__ xt) {
    int wid = threadIdx.x >> 5, lane = threadIdx.x & 31;
    int row = blockIdx.x * 8 + wid;
    const float* p = (row < BHALF) ? xs + (size_t)row * DD
                                   : xt + (size_t)(row - BHALF) * DD;
    float* q = g_x + (size_t)row * DD;
    float s = 0.f;
    #pragma unroll
    for (int i = 0; i < 8; i++) {
        float v = p[lane + 32 * i];
        uint32_t tv;
        asm("cvt.rna.tf32.f32 %0, %1;" : "=r"(tv) : "f"(v));
        float t = __uint_as_float(tv);
        q[lane + 32 * i] = t;
        s = fmaf(t, t, s);
    }
    #pragma unroll
    for (int o = 16; o; o >>= 1) s += __shfl_xor_sync(0xffffffffu, s, o);
    __shared__ float ws[8];
    if (lane == 0) { g_sq[row] = s; ws[wid] = s; }
    __syncthreads();
    if (threadIdx.x == 0) {
        float b = 0.f;
        #pragma unroll
        for (int w = 0; w < 8; w++) b += ws[w];
        g_sqpart[blockIdx.x] = b;
    }
}

__global__ void colsum_kernel() {
    int t = threadIdx.x;
    int r0 = blockIdx.x * 256;
    float s = 0.f;
    for (int r = r0; r < r0 + 256; r++) s += g_x[(size_t)r * DD + t];
    g_colpart[blockIdx.x * DD + t] = s;
}

__global__ void bw_kernel() {
    __shared__ double sh[256];
    int t = threadIdx.x;
    float cs = 0.f;
    #pragma unroll 4
    for (int b = 0; b < 32; b++) cs += g_colpart[b * DD + t];
    float sq = 0.f;
    #pragma unroll
    for (int i = 0; i < 4; i++) sq += g_sqpart[t + 256 * i];

    sh[t] = (double)cs * (double)cs;
    __syncthreads();
    for (int s2 = 128; s2; s2 >>= 1) { if (t < s2) sh[t] += sh[t + s2]; __syncthreads(); }
    double cs_tot = sh[0];
    __syncthreads();
    sh[t] = (double)sq;
    __syncthreads();
    for (int s2 = 128; s2; s2 >>= 1) { if (t < s2) sh[t] += sh[t + s2]; __syncthreads(); }
    if (t == 0) {
        double sumsq = sh[0];
        double n = (double)NTOT;
        double sumL2 = 2.0 * n * sumsq - 2.0 * cs_tot;
        double bw = sumL2 / (n * n - n) / 4.0;   // / KERNEL_MUL^(NUM//2)
        g_m = (float)(1.4426950408889634 / (bw * 16.0));
        g_acc = 0.0;
    }
}

// ---------------- chunk loader: 2048 x 16B, 8 per thread ----------------
__device__ __forceinline__ void load_chunk(uint32_t sb, int buf,
                                           const float* gA, const float* gB,
                                           int k0, int tid) {
    uint32_t aB = sb + buf * STAGE_BYTES;
    uint32_t bB = aB + B_OFF;
    #pragma unroll
    for (int i = 0; i < 4; i++) {
        int u = tid + i * 256;
        int row = u >> 3, c = u & 7;
        uint32_t off = (uint32_t)(row * 128 + c * 16);
        uint32_t sw = off ^ ((off >> 3) & 0x70);
        const float* srcA = gA + (size_t)row * DD + k0 + c * 4;
        const float* srcB = gB + (size_t)row * DD + k0 + c * 4;
        asm volatile("cp.async.cg.shared.global [%0], [%1], 16;"
                     :: "r"(aB + sw), "l"(srcA));
        asm volatile("cp.async.cg.shared.global [%0], [%1], 16;"
                     :: "r"(bB + sw), "l"(srcB));
    }
    asm volatile("cp.async.commit_group;" ::: "memory");
}

// ---------------- main tensor-core kernel ----------------
__global__ void __launch_bounds__(NT, 2) mmd_mma_kernel() {
    int ti = blockIdx.y, tj = blockIdx.x;
    if (tj > ti) return;                 // lower triangle of tile grid only
    extern __shared__ char smem[];
    uint32_t sb = smem_u32(smem);
    int tid = threadIdx.x, wid = tid >> 5, lane = tid & 31;

    const float* gA = g_x + (size_t)ti * TILE * DD;
    const float* gB = g_x + (size_t)tj * TILE * DD;

    load_chunk(sb, 0, gA, gB, 0, tid);

    int wm = (wid >> 2) * 64;            // warp M offset within tile
    int wn = (wid & 3) * 32;             // warp N offset

    float acc[4][4][4];
    #pragma unroll
    for (int a = 0; a < 4; a++)
        #pragma unroll
        for (int b = 0; b < 4; b++)
            #pragma unroll
            for (int c = 0; c < 4; c++) acc[a][b][c] = 0.f;

    int grp = lane >> 3, rin = lane & 7;
    int aRow = wm + (grp & 1) * 8 + rin;       // lane's ldmatrix row for A
    int aKB  = (grp >> 1) * 16;                // k byte offset within step
    int bRow = wn + (grp >> 1) * 8 + rin;      // lane's ldmatrix row for B
    int bKB  = (grp & 1) * 16;

    for (int ck = 0; ck < NCHUNK; ck++) {
        if (ck < NCHUNK - 1) {
            load_chunk(sb, (ck + 1) & 1, gA, gB, (ck + 1) * KC, tid);
            asm volatile("cp.async.wait_group 1;" ::: "memory");
        } else {
            asm volatile("cp.async.wait_group 0;" ::: "memory");
        }
        __syncthreads();

        uint32_t aB = sb + (uint32_t)(ck & 1) * STAGE_BYTES;
        uint32_t bB = aB + B_OFF;

        #pragma unroll
        for (int ks = 0; ks < 4; ks++) {       // four k8 steps per 32-float chunk
            uint32_t a[4][4], b[2][4];
            #pragma unroll
            for (int mt = 0; mt < 4; mt++) {
                uint32_t off = (uint32_t)((aRow + mt * 16) * 128 + aKB + ks * 32);
                ldsm_x4(a[mt][0], a[mt][1], a[mt][2], a[mt][3],
                        aB + (off ^ ((off >> 3) & 0x70)));
            }
            #pragma unroll
            for (int nh = 0; nh < 2; nh++) {
                uint32_t off = (uint32_t)((bRow + nh * 16) * 128 + bKB + ks * 32);
                ldsm_x4(b[nh][0], b[nh][1], b[nh][2], b[nh][3],
                        bB + (off ^ ((off >> 3) & 0x70)));
            }
            #pragma unroll
            for (int mt = 0; mt < 4; mt++)
                #pragma unroll
                for (int nt = 0; nt < 4; nt++)
                    mma_tf32(acc[mt][nt], a[mt],
                             b[nt >> 1][(nt & 1) * 2], b[nt >> 1][(nt & 1) * 2 + 1]);
        }
        __syncthreads();
    }

    // ---- epilogue: L2 -> 5-kernel RBF sum (one EX2 + 4 squarings) ----
    float m = g_m;
    int r0 = ti * TILE + wm + (lane >> 2);
    int c0 = tj * TILE + wn + ((lane & 3) << 1);
    float total = 0.f;
    #pragma unroll
    for (int mt = 0; mt < 4; mt++) {
        int rr = r0 + mt * 16;
        float sa0 = g_sq[rr], sa1 = g_sq[rr + 8];
        #pragma unroll
        for (int nt = 0; nt < 4; nt++) {
            int cc = c0 + nt * 8;
            float sb0 = g_sq[cc], sb1 = g_sq[cc + 1];
            #pragma unroll
            for (int e = 0; e < 4; e++) {
                int   rg = rr + ((e >> 1) << 3);
                int   cg = cc + (e & 1);
                float sa = (e >> 1) ? sa1 : sa0;
                float sbv = (e & 1) ? sb1 : sb0;
                float L2 = fmaxf(sa + sbv - 2.f * acc[mt][nt][e], 0.f);
                float e0;
                asm("ex2.approx.ftz.f32 %0, %1;" : "=f"(e0) : "f"(-L2 * m));
                float e1 = e0 * e0, e2 = e1 * e1, e3 = e2 * e2, e4 = e3 * e3;
                float kv = ((e0 + e1) + (e2 + e3)) + e4;
                total += (rg > cg) ? kv : 0.f;   // strict lower triangle
            }
        }
    }
    // sign(s_i s_j) * 2 (triangle symmetry)
    total *= (((ti < 32) == (tj < 32)) ? 2.f : -2.f);

    #pragma unroll
    for (int o = 16; o; o >>= 1) total += __shfl_xor_sync(0xffffffffu, total, o);
    __syncthreads();                      // smem no longer needed for tiles
    float* red = (float*)smem;
    if (lane == 0) red[wid] = total;
    __syncthreads();
    if (tid == 0) {
        float s = 0.f;
        #pragma unroll
        for (int w = 0; w < 8; w++) s += red[w];
        atomicAdd(&g_acc, (double)s);
    }
}

__global__ void finalize_kernel(float* __restrict__ out) {
    // diagonal of the big kernel matrix contributes NTOT * 5 (k(0)=1 per kernel)
    out[0] = (float)((g_acc + (double)NTOT * 5.0) /
                     ((double)BHALF * (double)BHALF));
}

// ---------------- launch ----------------
extern "C" void kernel_launch(void* const* d_in, const int* in_sizes, int n_in,
                              void* d_out, int out_size) {
    const float* xs = (const float*)d_in[0];
    const float* xt = (const float*)d_in[1];
    float* out = (float*)d_out;

    cudaFuncSetAttribute(mmd_mma_kernel,
                         cudaFuncAttributeMaxDynamicSharedMemorySize, SMEM_TOTAL);

    convert_kernel<<<NTOT / 8, 256>>>(xs, xt);
    colsum_kernel<<<32, 256>>>();
    bw_kernel<<<1, 256>>>();
    mmd_mma_kernel<<<dim3(64, 64), NT, SMEM_TOTAL>>>();
    finalize_kernel<<<1, 1>>>(out);
}

// round 4
// speedup vs baseline: 5.7500x; 1.5013x over previous
#include <cuda_runtime.h>
#include <cuda_fp16.h>
#include <cstdint>

// ---------------- problem constants ----------------
#define NTOT   8192
#define BHALF  4096
#define DD     256
#define TILE   128
#define KC     64       // K-chunk halves = 128 B/row (SW128 atom)
#define NCHUNK 4        // 256 / 64
#define NT     256      // threads per CTA (8 warps, 2x4 warp grid)
#define NTILES 64
#define NBLK   (NTILES * (NTILES + 1) / 2)   // 2080

// smem: [A0 16K][B0 16K][A1 16K][B1 16K] = 64 KB dynamic
#define STAGE_BYTES 32768u
#define B_OFF       16384u
#define SMEM_TOTAL  65536

// ---------------- device scratch (no allocs allowed) ----------------
__device__ __half g_x[NTOT * DD];      // fp16-rounded inputs, concatenated
__device__ float  g_sq[NTOT];          // row squared norms of rounded data
__device__ float  g_sqpart[1024];
__device__ float  g_colsum[DD];        // zero-init; bw_kernel resets after use
__device__ float  g_m;                 // log2(e) / (16 * bandwidth)
__device__ double g_acc;

// ---------------- helpers ----------------
__device__ __forceinline__ uint32_t smem_u32(const void* p) {
    uint32_t a;
    asm("{ .reg .u64 t; cvta.to.shared.u64 t, %1; cvt.u32.u64 %0, t; }"
        : "=r"(a) : "l"(p));
    return a;
}

__device__ __forceinline__ void ldsm_x4(uint32_t& r0, uint32_t& r1,
                                        uint32_t& r2, uint32_t& r3,
                                        uint32_t addr) {
    asm volatile("ldmatrix.sync.aligned.m8n8.x4.shared.b16 {%0,%1,%2,%3}, [%4];"
                 : "=r"(r0), "=r"(r1), "=r"(r2), "=r"(r3) : "r"(addr));
}

__device__ __forceinline__ void mma_f16(float* d, const uint32_t* a,
                                        uint32_t b0, uint32_t b1) {
    asm volatile(
        "mma.sync.aligned.m16n8k16.row.col.f32.f16.f16.f32 "
        "{%0,%1,%2,%3}, {%4,%5,%6,%7}, {%8,%9}, {%0,%1,%2,%3};"
        : "+f"(d[0]), "+f"(d[1]), "+f"(d[2]), "+f"(d[3])
        : "r"(a[0]), "r"(a[1]), "r"(a[2]), "r"(a[3]), "r"(b0), "r"(b1));
}

// ---------------- prep: round to fp16, row norms, column sums ----------------
__global__ void convert_kernel(const float* __restrict__ xs,
                               const float* __restrict__ xt) {
    int wid = threadIdx.x >> 5, lane = threadIdx.x & 31;
    int row = blockIdx.x * 8 + wid;
    const float* p = (row < BHALF) ? xs + (size_t)row * DD
                                   : xt + (size_t)(row - BHALF) * DD;
    __half* q = g_x + (size_t)row * DD;

    __shared__ float scol[DD];
    scol[threadIdx.x] = 0.f;
    __syncthreads();

    // lane handles 8 contiguous columns [lane*8, lane*8+8)
    int c0 = lane * 8;
    float4 v0 = *(const float4*)(p + c0);
    float4 v1 = *(const float4*)(p + c0 + 4);
    float f[8] = {v0.x, v0.y, v0.z, v0.w, v1.x, v1.y, v1.z, v1.w};
    float s = 0.f, csum = 0.f;
    half2* q2 = (half2*)(q + c0);
    #pragma unroll
    for (int j = 0; j < 4; j++) {
        __half h0 = __float2half_rn(f[2 * j]);
        __half h1 = __float2half_rn(f[2 * j + 1]);
        q2[j] = __halves2half2(h0, h1);
        float t0 = __half2float(h0), t1 = __half2float(h1);
        s = fmaf(t0, t0, s); s = fmaf(t1, t1, s);
        f[2 * j] = t0; f[2 * j + 1] = t1;
    }
    #pragma unroll
    for (int j = 0; j < 8; j++) csum += 0.f;   // (placeholder, col adds below)
    #pragma unroll
    for (int j = 0; j < 8; j++) atomicAdd(&scol[c0 + j], f[j]);

    #pragma unroll
    for (int o = 16; o; o >>= 1) s += __shfl_xor_sync(0xffffffffu, s, o);
    __shared__ float ws[8];
    if (lane == 0) ws[wid] = s;
    if (lane == 0) g_sq[row] = s;
    __syncthreads();
    if (threadIdx.x == 0) {
        float b = 0.f;
        #pragma unroll
        for (int w = 0; w < 8; w++) b += ws[w];
        g_sqpart[blockIdx.x] = b;
    }
    atomicAdd(&g_colsum[threadIdx.x], scol[threadIdx.x]);
}

__global__ void bw_kernel() {
    __shared__ double sh[256];
    int t = threadIdx.x;
    float cs = g_colsum[t];
    float sq = 0.f;
    #pragma unroll
    for (int i = 0; i < 4; i++) sq += g_sqpart[t + 256 * i];

    sh[t] = (double)cs * (double)cs;
    __syncthreads();
    for (int s2 = 128; s2; s2 >>= 1) { if (t < s2) sh[t] += sh[t + s2]; __syncthreads(); }
    double cs_tot = sh[0];
    __syncthreads();
    sh[t] = (double)sq;
    __syncthreads();
    for (int s2 = 128; s2; s2 >>= 1) { if (t < s2) sh[t] += sh[t + s2]; __syncthreads(); }
    if (t == 0) {
        double sumsq = sh[0];
        double n = (double)NTOT;
        double sumL2 = 2.0 * n * sumsq - 2.0 * cs_tot;
        double bw = sumL2 / (n * n - n) / 4.0;   // / KERNEL_MUL^(NUM//2)
        g_m = (float)(1.4426950408889634 / (bw * 16.0));
        g_acc = 0.0;
    }
    g_colsum[t] = 0.f;   // reset for next graph replay (after use)
}

// ---------------- chunk loader: 2048 x 16B, 8 per thread ----------------
__device__ __forceinline__ void load_chunk(uint32_t sb, int buf,
                                           const __half* gA, const __half* gB,
                                           int k0, int tid) {
    uint32_t aB = sb + buf * STAGE_BYTES;
    uint32_t bB = aB + B_OFF;
    #pragma unroll
    for (int i = 0; i < 4; i++) {
        int u = tid + i * 256;
        int row = u >> 3, c = u & 7;
        uint32_t off = (uint32_t)(row * 128 + c * 16);
        uint32_t sw = off ^ ((off >> 3) & 0x70);
        const __half* srcA = gA + (size_t)row * DD + k0 + c * 8;
        const __half* srcB = gB + (size_t)row * DD + k0 + c * 8;
        asm volatile("cp.async.cg.shared.global [%0], [%1], 16;"
                     :: "r"(aB + sw), "l"(srcA));
        asm volatile("cp.async.cg.shared.global [%0], [%1], 16;"
                     :: "r"(bB + sw), "l"(srcB));
    }
    asm volatile("cp.async.commit_group;" ::: "memory");
}

// ---------------- main tensor-core kernel ----------------
__global__ void __launch_bounds__(NT, 2) mmd_mma_kernel() {
    // linear -> triangular (ti >= tj)
    int b = blockIdx.x;
    int ti = (int)((sqrtf(8.f * (float)b + 1.f) - 1.f) * 0.5f);
    while ((ti + 1) * (ti + 2) / 2 <= b) ti++;
    while (ti * (ti + 1) / 2 > b) ti--;
    int tj = b - ti * (ti + 1) / 2;

    extern __shared__ char smem[];
    uint32_t sb = smem_u32(smem);
    int tid = threadIdx.x, wid = tid >> 5, lane = tid & 31;

    const __half* gA = g_x + (size_t)ti * TILE * DD;
    const __half* gB = g_x + (size_t)tj * TILE * DD;

    load_chunk(sb, 0, gA, gB, 0, tid);

    int wm = (wid >> 2) * 64;            // warp M offset within tile
    int wn = (wid & 3) * 32;             // warp N offset

    float acc[4][4][4];
    #pragma unroll
    for (int a = 0; a < 4; a++)
        #pragma unroll
        for (int c = 0; c < 4; c++)
            #pragma unroll
            for (int e = 0; e < 4; e++) acc[a][c][e] = 0.f;

    int grp = lane >> 3, rin = lane & 7;
    // A: lane -> row wm + mt*16 + (grp&1)*8 + rin, k-byte (grp>>1)*16
    int aRow = wm + (grp & 1) * 8 + rin;
    int aKB  = (grp >> 1) * 16;
    // B: lane -> row wn + nh*16 + (grp>>1)*8 + rin, k-byte (grp&1)*16
    int bRow = wn + (grp >> 1) * 8 + rin;
    int bKB  = (grp & 1) * 16;

    // swizzle folds to: addr = row*128 + ((x) ^ ((row&7)<<4)), x < 128
    uint32_t aMask = (uint32_t)((aRow & 7) << 4);
    uint32_t bMask = (uint32_t)((bRow & 7) << 4);

    for (int ck = 0; ck < NCHUNK; ck++) {
        if (ck < NCHUNK - 1) {
            load_chunk(sb, (ck + 1) & 1, gA, gB, (ck + 1) * KC, tid);
            asm volatile("cp.async.wait_group 1;" ::: "memory");
        } else {
            asm volatile("cp.async.wait_group 0;" ::: "memory");
        }
        __syncthreads();

        uint32_t aB = sb + (uint32_t)(ck & 1) * STAGE_BYTES;
        uint32_t bB = aB + B_OFF;

        #pragma unroll
        for (int ks = 0; ks < 4; ks++) {     // four k16 steps per 64-half chunk
            uint32_t a[4][4], bf[2][4];
            #pragma unroll
            for (int mt = 0; mt < 4; mt++) {
                uint32_t addr = aB + (uint32_t)((aRow + mt * 16) * 128)
                              + (((uint32_t)(ks * 32 + aKB)) ^ aMask);
                ldsm_x4(a[mt][0], a[mt][1], a[mt][2], a[mt][3], addr);
            }
            #pragma unroll
            for (int nh = 0; nh < 2; nh++) {
                uint32_t addr = bB + (uint32_t)((bRow + nh * 16) * 128)
                              + (((uint32_t)(ks * 32 + bKB)) ^ bMask);
                ldsm_x4(bf[nh][0], bf[nh][1], bf[nh][2], bf[nh][3], addr);
            }
            #pragma unroll
            for (int mt = 0; mt < 4; mt++)
                #pragma unroll
                for (int nt = 0; nt < 4; nt++)
                    mma_f16(acc[mt][nt], a[mt],
                            bf[nt >> 1][(nt & 1) * 2], bf[nt >> 1][(nt & 1) * 2 + 1]);
        }
        __syncthreads();
    }

    // ---- epilogue: L2 -> 5-kernel RBF sum (one EX2 + 4 squarings) ----
    float m = g_m;
    int r0 = ti * TILE + wm + (lane >> 2);
    int c0 = tj * TILE + wn + ((lane & 3) << 1);
    float total = 0.f;
    #pragma unroll
    for (int mt = 0; mt < 4; mt++) {
        int rr = r0 + mt * 16;
        float sa0 = g_sq[rr], sa1 = g_sq[rr + 8];
        #pragma unroll
        for (int nt = 0; nt < 4; nt++) {
            int cc = c0 + nt * 8;
            float sb0 = g_sq[cc], sb1 = g_sq[cc + 1];
            #pragma unroll
            for (int e = 0; e < 4; e++) {
                int   rg = rr + ((e >> 1) << 3);
                int   cg = cc + (e & 1);
                float sa  = (e >> 1) ? sa1 : sa0;
                float sbv = (e & 1) ? sb1 : sb0;
                float L2 = fmaxf(sa + sbv - 2.f * acc[mt][nt][e], 0.f);
                float e0;
                asm("ex2.approx.ftz.f32 %0, %1;" : "=f"(e0) : "f"(-L2 * m));
                float e1 = e0 * e0, e2 = e1 * e1, e3 = e2 * e2, e4 = e3 * e3;
                float kv = ((e0 + e1) + (e2 + e3)) + e4;
                total += (rg > cg) ? kv : 0.f;   // strict lower triangle
            }
        }
    }
    // sign(s_i s_j) * 2 (triangle symmetry)
    total *= (((ti < 32) == (tj < 32)) ? 2.f : -2.f);

    #pragma unroll
    for (int o = 16; o; o >>= 1) total += __shfl_xor_sync(0xffffffffu, total, o);
    __syncthreads();
    float* red = (float*)smem;
    if (lane == 0) red[wid] = total;
    __syncthreads();
    if (tid == 0) {
        float s = 0.f;
        #pragma unroll
        for (int w = 0; w < 8; w++) s += red[w];
        atomicAdd(&g_acc, (double)s);
    }
}

__global__ void finalize_kernel(float* __restrict__ out) {
    // diagonal of the big kernel matrix contributes NTOT * 5 (k(0)=1 per kernel)
    out[0] = (float)((g_acc + (double)NTOT * 5.0) /
                     ((double)BHALF * (double)BHALF));
}

// ---------------- launch ----------------
extern "C" void kernel_launch(void* const* d_in, const int* in_sizes, int n_in,
                              void* d_out, int out_size) {
    const float* xs = (const float*)d_in[0];
    const float* xt = (const float*)d_in[1];
    float* out = (float*)d_out;

    cudaFuncSetAttribute(mmd_mma_kernel,
                         cudaFuncAttributeMaxDynamicSharedMemorySize, SMEM_TOTAL);

    convert_kernel<<<NTOT / 8, 256>>>(xs, xt);
    bw_kernel<<<1, 256>>>();
    mmd_mma_kernel<<<NBLK, NT, SMEM_TOTAL>>>();
    finalize_kernel<<<1, 1>>>(out);
}